// round 2
// baseline (speedup 1.0000x reference)
#include <cuda_runtime.h>
#include <cstddef>

#define EMB 384
#define NMAX 50000

// Scratch (static __device__ arrays; no allocation anywhere)
__device__ float g_bufA[(size_t)NMAX * EMB];
__device__ float g_bufB[(size_t)NMAX * EMB];
__device__ float g_bufC[(size_t)NMAX * EMB];
__device__ float g_dinv[NMAX];

template <int SEL>
__device__ __forceinline__ float* BUF() {
    if constexpr (SEL == 0) return g_bufA;
    else if constexpr (SEL == 1) return g_bufB;
    else return g_bufC;
}

__device__ __forceinline__ float leaky01(float x) { return x > 0.f ? x : 0.01f * x; }

// ---------------------------------------------------------------------------
// fp32 GEMM: C[M,Nc] = act(A[M,K] @ B[K,Nc] + bias)
// 64x64 block tile, BK=16, 4x4 per thread. Requires K%16==0, Nc%64==0.
// SRC = -1 -> A comes from the Ain pointer (harness input); else scratch SEL.
// ---------------------------------------------------------------------------
template <int SRC, int DST, int HAS_BIAS, int ACT>
__global__ void __launch_bounds__(256) sgemm(
    const float* __restrict__ Ain, const float* __restrict__ B,
    const float* __restrict__ bias,
    int M, int K, int Nc, int ldc, int coff)
{
    const float* __restrict__ A;
    if constexpr (SRC < 0) A = Ain; else A = BUF<SRC>();
    float* __restrict__ C = BUF<DST>();

    __shared__ float As[16][65];   // [k][m], padded vs bank conflicts
    __shared__ float Bs[16][64];   // [k][n]

    const int tid = threadIdx.x;
    const int tx = tid & 15;
    const int ty = tid >> 4;
    const int row0 = blockIdx.y * 64;
    const int col0 = blockIdx.x * 64;

    float acc[4][4] = {};

    for (int k0 = 0; k0 < K; k0 += 16) {
        #pragma unroll
        for (int i = 0; i < 4; i++) {
            int idx = i * 256 + tid;       // 0..1023
            int r = idx >> 4, c = idx & 15;
            int gr = row0 + r;
            As[c][r] = (gr < M) ? A[(size_t)gr * K + (k0 + c)] : 0.f;
        }
        #pragma unroll
        for (int i = 0; i < 4; i++) {
            int idx = i * 256 + tid;
            int r = idx >> 6, c = idx & 63;
            Bs[r][c] = B[(size_t)(k0 + r) * Nc + (col0 + c)];
        }
        __syncthreads();

        #pragma unroll
        for (int kk = 0; kk < 16; kk++) {
            float a[4], b[4];
            #pragma unroll
            for (int i = 0; i < 4; i++) a[i] = As[kk][ty * 4 + i];
            #pragma unroll
            for (int j = 0; j < 4; j++) b[j] = Bs[kk][tx * 4 + j];
            #pragma unroll
            for (int i = 0; i < 4; i++)
                #pragma unroll
                for (int j = 0; j < 4; j++)
                    acc[i][j] += a[i] * b[j];
        }
        __syncthreads();
    }

    #pragma unroll
    for (int i = 0; i < 4; i++) {
        int gr = row0 + ty * 4 + i;
        if (gr >= M) continue;
        #pragma unroll
        for (int j = 0; j < 4; j++) {
            int gc = col0 + tx * 4 + j;
            float v = acc[i][j];
            if (HAS_BIAS) v += bias[gc];
            if (ACT) v = leaky01(v);
            C[(size_t)gr * ldc + coff + gc] = v;
        }
    }
}

// ---------------------------------------------------------------------------
// num/cat feature linears (K=4, K=3) -> concat columns [128:256), [256:384)
// of g_bufA. One thread per (node, col<128).
// ---------------------------------------------------------------------------
__global__ void numcat_kernel(
    const float* __restrict__ np_, const float* __restrict__ cp,
    const float* __restrict__ Wn, const float* __restrict__ bn,
    const float* __restrict__ Wc, const float* __restrict__ bc, int N)
{
    int i = blockIdx.x * blockDim.x + threadIdx.x;
    int node = i >> 7;
    int col = i & 127;
    if (node >= N) return;

    float s = bn[col];
    #pragma unroll
    for (int k = 0; k < 4; k++) s += np_[node * 4 + k] * Wn[k * 128 + col];
    g_bufA[(size_t)node * EMB + 128 + col] = leaky01(s);

    float t = bc[col];
    #pragma unroll
    for (int k = 0; k < 3; k++) t += cp[node * 3 + k] * Wc[k * 128 + col];
    g_bufA[(size_t)node * EMB + 256 + col] = leaky01(t);
}

// ---------------------------------------------------------------------------
// Degree / normalization (edge_index is int32: JAX randint int64 silently
// falls back to int32 with x64 disabled)
// ---------------------------------------------------------------------------
__global__ void zero_dinv(int N)
{
    int i = blockIdx.x * blockDim.x + threadIdx.x;
    if (i < N) g_dinv[i] = 0.f;
}

__global__ void count_deg(const int* __restrict__ ei, int E)
{
    int e = blockIdx.x * blockDim.x + threadIdx.x;
    if (e < E) {
        int d = ei[E + e];
        atomicAdd(&g_dinv[d], 1.0f);
    }
}

__global__ void finish_dinv(int N)
{
    int i = blockIdx.x * blockDim.x + threadIdx.x;
    if (i < N) g_dinv[i] = rsqrtf(g_dinv[i] + 1.0f);   // deg + self-loop
}

// ---------------------------------------------------------------------------
// GCN aggregation. agg = xw * dinv^2 + bias (self-loop), then per edge (s,d):
// agg[d,:] += xw[s,:] * dinv[s]*dinv[d]
// ---------------------------------------------------------------------------
template <int SRC, int DST>
__global__ void agg_init(const float* __restrict__ bias, int total)
{
    const float* __restrict__ xw = BUF<SRC>();
    float* __restrict__ agg = BUF<DST>();
    int i = blockIdx.x * blockDim.x + threadIdx.x;
    if (i >= total) return;
    int node = i / EMB;
    int col = i - node * EMB;
    float di = g_dinv[node];
    agg[i] = xw[i] * di * di + bias[col];
}

template <int SRC, int DST>
__global__ void edge_scatter(const int* __restrict__ ei, int E)
{
    const float* __restrict__ xw = BUF<SRC>();
    float* __restrict__ agg = BUF<DST>();

    int warp = (blockIdx.x * blockDim.x + threadIdx.x) >> 5;
    int lane = threadIdx.x & 31;
    if (warp >= E) return;

    int src = ei[warp];
    int dst = ei[E + warp];
    float norm = g_dinv[src] * g_dinv[dst];

    const float4* xs = (const float4*)(xw + (size_t)src * EMB);
    float* ad = agg + (size_t)dst * EMB;

    #pragma unroll
    for (int it = 0; it < 3; it++) {
        int j4 = it * 32 + lane;          // 96 float4 = 384 floats
        float4 v = xs[j4];
        int j = j4 * 4;
        atomicAdd(ad + j + 0, v.x * norm);
        atomicAdd(ad + j + 1, v.y * norm);
        atomicAdd(ad + j + 2, v.z * norm);
        atomicAdd(ad + j + 3, v.w * norm);
    }
}

// ---------------------------------------------------------------------------
// Final projection to 2 logits from g_bufA: one warp per node.
// ---------------------------------------------------------------------------
__global__ void out_kernel(
    const float* __restrict__ W, const float* __restrict__ b,
    float* __restrict__ out, int N)
{
    int warp = (blockIdx.x * blockDim.x + threadIdx.x) >> 5;
    int lane = threadIdx.x & 31;
    if (warp >= N) return;

    const float* x = g_bufA + (size_t)warp * EMB;
    float s0 = 0.f, s1 = 0.f;
    #pragma unroll
    for (int it = 0; it < EMB / 32; it++) {
        int j = it * 32 + lane;
        float v = x[j];
        s0 += v * W[j * 2 + 0];
        s1 += v * W[j * 2 + 1];
    }
    #pragma unroll
    for (int o = 16; o > 0; o >>= 1) {
        s0 += __shfl_down_sync(0xFFFFFFFFu, s0, o);
        s1 += __shfl_down_sync(0xFFFFFFFFu, s1, o);
    }
    if (lane == 0) {
        out[(size_t)warp * 2 + 0] = s0 + b[0];
        out[(size_t)warp * 2 + 1] = s1 + b[1];
    }
}

// ---------------------------------------------------------------------------
// Launcher — kernel launches only (graph-capturable, allocation-free)
// ---------------------------------------------------------------------------
extern "C" void kernel_launch(void* const* d_in, const int* in_sizes, int n_in,
                              void* d_out, int out_size)
{
    const float* des = (const float*)d_in[0];
    // d_in[1] = tweet — unused by the reference model
    const float* np_ = (const float*)d_in[2];
    const float* cp  = (const float*)d_in[3];
    const int*   ei  = (const int*)d_in[4];
    const float* W_des = (const float*)d_in[5];  const float* b_des = (const float*)d_in[6];
    const float* W_num = (const float*)d_in[7];  const float* b_num = (const float*)d_in[8];
    const float* W_cat = (const float*)d_in[9];  const float* b_cat = (const float*)d_in[10];
    const float* W_in  = (const float*)d_in[11]; const float* b_in  = (const float*)d_in[12];
    const float* W_g1  = (const float*)d_in[13]; const float* b_g1  = (const float*)d_in[14];
    const float* W_g2  = (const float*)d_in[15]; const float* b_g2  = (const float*)d_in[16];
    const float* W_o1  = (const float*)d_in[17]; const float* b_o1  = (const float*)d_in[18];
    const float* W_o2  = (const float*)d_in[19]; const float* b_o2  = (const float*)d_in[20];

    const int N = in_sizes[0] / 768;
    const int E = in_sizes[4] / 2;

    const int mb = (N + 63) / 64;
    const int total = N * EMB;

    // --- degree / dinv ---
    zero_dinv<<<(N + 255) / 256, 256>>>(N);
    count_deg<<<(E + 255) / 256, 256>>>(ei, E);
    finish_dinv<<<(N + 255) / 256, 256>>>(N);

    // --- feature embedding: bufA = concat of 3 leaky-linears ---
    sgemm<-1, 0, 1, 1><<<dim3(2, mb), 256>>>(des, W_des, b_des, N, 768, 128, EMB, 0);
    numcat_kernel<<<(N * 128 + 255) / 256, 256>>>(np_, cp, W_num, b_num, W_cat, b_cat, N);

    // --- input linear: bufB = leaky(bufA @ W_in + b_in) ---
    sgemm<0, 1, 1, 1><<<dim3(6, mb), 256>>>(nullptr, W_in, b_in, N, EMB, EMB, EMB, 0);

    // --- GCN conv 1: bufC = bufB @ W_g1 ; bufA = agg(bufC) + b_g1 ---
    sgemm<1, 2, 0, 0><<<dim3(6, mb), 256>>>(nullptr, W_g1, nullptr, N, EMB, EMB, EMB, 0);
    agg_init<2, 0><<<(total + 255) / 256, 256>>>(b_g1, total);
    edge_scatter<2, 0><<<(int)(((size_t)E * 32 + 255) / 256), 256>>>(ei, E);

    // --- GCN conv 2: bufC = bufA @ W_g2 ; bufB = agg(bufC) + b_g2 ---
    sgemm<0, 2, 0, 0><<<dim3(6, mb), 256>>>(nullptr, W_g2, nullptr, N, EMB, EMB, EMB, 0);
    agg_init<2, 1><<<(total + 255) / 256, 256>>>(b_g2, total);
    edge_scatter<2, 1><<<(int)(((size_t)E * 32 + 255) / 256), 256>>>(ei, E);

    // --- output head: bufA = leaky(bufB @ W_o1 + b_o1); out = bufA @ W_o2 + b_o2 ---
    sgemm<1, 0, 1, 1><<<dim3(6, mb), 256>>>(nullptr, W_o1, b_o1, N, EMB, EMB, EMB, 0);
    out_kernel<<<(int)(((size_t)N * 32 + 255) / 256), 256>>>(W_o2, b_o2, (float*)d_out, N);
}

// round 3
// speedup vs baseline: 1.8786x; 1.8786x over previous
#include <cuda_runtime.h>
#include <cstddef>
#include <cstdint>

#define EMB 384
#define NMAX 50000

// Scratch (static __device__ arrays; no allocation anywhere)
__device__ float g_bufA[(size_t)NMAX * EMB];
__device__ float g_bufB[(size_t)NMAX * EMB];
__device__ float g_bufC[(size_t)NMAX * EMB];
__device__ float g_dinv[NMAX];

template <int SEL>
__device__ __forceinline__ float* BUF() {
    if constexpr (SEL == 0) return g_bufA;
    else if constexpr (SEL == 1) return g_bufB;
    else return g_bufC;
}

__device__ __forceinline__ float leaky01(float x) { return x > 0.f ? x : 0.01f * x; }

__device__ __forceinline__ float to_tf32(float x) {
    uint32_t u;
    asm("cvt.rna.tf32.f32 %0, %1;" : "=r"(u) : "f"(x));
    return __uint_as_float(u);
}

__device__ __forceinline__ void mma_tf32(
    float& c0, float& c1, float& c2, float& c3,
    uint32_t a0, uint32_t a1, uint32_t a2, uint32_t a3,
    uint32_t b0, uint32_t b1)
{
    asm volatile(
        "mma.sync.aligned.m16n8k8.row.col.f32.tf32.tf32.f32 "
        "{%0,%1,%2,%3}, {%4,%5,%6,%7}, {%8,%9}, {%0,%1,%2,%3};"
        : "+f"(c0), "+f"(c1), "+f"(c2), "+f"(c3)
        : "r"(a0), "r"(a1), "r"(a2), "r"(a3), "r"(b0), "r"(b1));
}

// ---------------------------------------------------------------------------
// tf32 tensor-core GEMM: C[M,Nc] = act(A[M,K] @ B[K,Nc] + bias)
// BM=128, BN=64, BK=32. 8 warps: 4 (m) x 2 (n), each warp 32x32 output via
// 2x4 m16n8k8 mma tiles. Requires K%32==0, Nc%64==0.
// SRC = -1 -> A from Ain pointer; else scratch BUF<SRC>. C into BUF<DST>.
// ---------------------------------------------------------------------------
template <int SRC, int DST, int HAS_BIAS, int ACT>
__global__ void __launch_bounds__(256) tgemm(
    const float* __restrict__ Ain, const float* __restrict__ B,
    const float* __restrict__ bias,
    int M, int K, int Nc, int ldc, int coff)
{
    const float* __restrict__ A;
    if constexpr (SRC < 0) A = Ain; else A = BUF<SRC>();
    float* __restrict__ C = BUF<DST>();

    __shared__ float As[32][132];   // [k][m], padded
    __shared__ float Bs[32][68];    // [k][n], padded (row stride 272B, 16B-aligned)

    const int tid = threadIdx.x;
    const int lane = tid & 31;
    const int warp = tid >> 5;
    const int warp_m = warp & 3;          // 4 warps along M (32 rows each)
    const int warp_n = warp >> 2;         // 2 warps along N (32 cols each)
    const int gid = lane >> 2;            // 0..7
    const int tig = lane & 3;             // 0..3

    const int row0 = blockIdx.y * 128;
    const int col0 = blockIdx.x * 64;

    float c[2][4][4];
    #pragma unroll
    for (int i = 0; i < 2; i++)
        #pragma unroll
        for (int j = 0; j < 4; j++)
            #pragma unroll
            for (int q = 0; q < 4; q++) c[i][j][q] = 0.f;

    // loader coords
    const int a_r = tid >> 3;             // 0..31 (row within tile, +32 steps)
    const int a_c = (tid & 7) * 4;        // k col
    const int b_r = tid >> 4;             // 0..15 (+16 step)
    const int b_c = (tid & 15) * 4;       // n col

    for (int k0 = 0; k0 < K; k0 += 32) {
        // A tile: 128 rows x 32 k -> As[k][m] (transposed), tf32-rounded
        #pragma unroll
        for (int i = 0; i < 4; i++) {
            int r = a_r + i * 32;
            int gr = row0 + r;
            float4 v = make_float4(0.f, 0.f, 0.f, 0.f);
            if (gr < M) v = *(const float4*)(A + (size_t)gr * K + k0 + a_c);
            As[a_c + 0][r] = to_tf32(v.x);
            As[a_c + 1][r] = to_tf32(v.y);
            As[a_c + 2][r] = to_tf32(v.z);
            As[a_c + 3][r] = to_tf32(v.w);
        }
        // B tile: 32 k x 64 n -> Bs[k][n], tf32-rounded
        #pragma unroll
        for (int i = 0; i < 2; i++) {
            int r = b_r + i * 16;
            float4 v = *(const float4*)(B + (size_t)(k0 + r) * Nc + col0 + b_c);
            v.x = to_tf32(v.x); v.y = to_tf32(v.y);
            v.z = to_tf32(v.z); v.w = to_tf32(v.w);
            *(float4*)&Bs[r][b_c] = v;
        }
        __syncthreads();

        #pragma unroll
        for (int ks = 0; ks < 32; ks += 8) {
            uint32_t af[2][4], bf[4][2];
            #pragma unroll
            for (int tm = 0; tm < 2; tm++) {
                int mrow = warp_m * 32 + tm * 16 + gid;
                af[tm][0] = __float_as_uint(As[ks + tig][mrow]);
                af[tm][1] = __float_as_uint(As[ks + tig][mrow + 8]);
                af[tm][2] = __float_as_uint(As[ks + tig + 4][mrow]);
                af[tm][3] = __float_as_uint(As[ks + tig + 4][mrow + 8]);
            }
            #pragma unroll
            for (int tn = 0; tn < 4; tn++) {
                int ncol = warp_n * 32 + tn * 8 + gid;
                bf[tn][0] = __float_as_uint(Bs[ks + tig][ncol]);
                bf[tn][1] = __float_as_uint(Bs[ks + tig + 4][ncol]);
            }
            #pragma unroll
            for (int tm = 0; tm < 2; tm++)
                #pragma unroll
                for (int tn = 0; tn < 4; tn++)
                    mma_tf32(c[tm][tn][0], c[tm][tn][1], c[tm][tn][2], c[tm][tn][3],
                             af[tm][0], af[tm][1], af[tm][2], af[tm][3],
                             bf[tn][0], bf[tn][1]);
        }
        __syncthreads();
    }

    // Epilogue: c0/c1 at (row, 2*tig), c2/c3 at (row+8, 2*tig)
    #pragma unroll
    for (int tm = 0; tm < 2; tm++) {
        int rbase = row0 + warp_m * 32 + tm * 16 + gid;
        #pragma unroll
        for (int tn = 0; tn < 4; tn++) {
            int gc = col0 + warp_n * 32 + tn * 8 + 2 * tig;
            float bx = 0.f, by = 0.f;
            if (HAS_BIAS) { bx = bias[gc]; by = bias[gc + 1]; }
            #pragma unroll
            for (int half = 0; half < 2; half++) {
                int gr = rbase + half * 8;
                if (gr >= M) continue;
                float v0 = c[tm][tn][half * 2 + 0] + bx;
                float v1 = c[tm][tn][half * 2 + 1] + by;
                if (ACT) { v0 = leaky01(v0); v1 = leaky01(v1); }
                float2 out = make_float2(v0, v1);
                *(float2*)(C + (size_t)gr * ldc + coff + gc) = out;
            }
        }
    }
}

// ---------------------------------------------------------------------------
// num/cat feature linears (K=4, K=3) -> concat columns [128:256), [256:384)
// ---------------------------------------------------------------------------
__global__ void numcat_kernel(
    const float* __restrict__ np_, const float* __restrict__ cp,
    const float* __restrict__ Wn, const float* __restrict__ bn,
    const float* __restrict__ Wc, const float* __restrict__ bc, int N)
{
    int i = blockIdx.x * blockDim.x + threadIdx.x;
    int node = i >> 7;
    int col = i & 127;
    if (node >= N) return;

    float s = bn[col];
    #pragma unroll
    for (int k = 0; k < 4; k++) s += np_[node * 4 + k] * Wn[k * 128 + col];
    g_bufA[(size_t)node * EMB + 128 + col] = leaky01(s);

    float t = bc[col];
    #pragma unroll
    for (int k = 0; k < 3; k++) t += cp[node * 3 + k] * Wc[k * 128 + col];
    g_bufA[(size_t)node * EMB + 256 + col] = leaky01(t);
}

// ---------------------------------------------------------------------------
// Degree / normalization (edge_index is int32)
// ---------------------------------------------------------------------------
__global__ void zero_dinv(int N)
{
    int i = blockIdx.x * blockDim.x + threadIdx.x;
    if (i < N) g_dinv[i] = 0.f;
}

__global__ void count_deg(const int* __restrict__ ei, int E)
{
    int e = blockIdx.x * blockDim.x + threadIdx.x;
    if (e < E) atomicAdd(&g_dinv[ei[E + e]], 1.0f);
}

__global__ void finish_dinv(int N)
{
    int i = blockIdx.x * blockDim.x + threadIdx.x;
    if (i < N) g_dinv[i] = rsqrtf(g_dinv[i] + 1.0f);
}

// ---------------------------------------------------------------------------
// GCN aggregation
// ---------------------------------------------------------------------------
template <int SRC, int DST>
__global__ void agg_init(const float* __restrict__ bias, int total)
{
    const float* __restrict__ xw = BUF<SRC>();
    float* __restrict__ agg = BUF<DST>();
    int i = blockIdx.x * blockDim.x + threadIdx.x;
    if (i >= total) return;
    int node = i / EMB;
    int col = i - node * EMB;
    float di = g_dinv[node];
    agg[i] = xw[i] * di * di + bias[col];
}

template <int SRC, int DST>
__global__ void edge_scatter(const int* __restrict__ ei, int E)
{
    const float* __restrict__ xw = BUF<SRC>();
    float* __restrict__ agg = BUF<DST>();

    int warp = (blockIdx.x * blockDim.x + threadIdx.x) >> 5;
    int lane = threadIdx.x & 31;
    if (warp >= E) return;

    int src = ei[warp];
    int dst = ei[E + warp];
    float norm = g_dinv[src] * g_dinv[dst];

    const float4* xs = (const float4*)(xw + (size_t)src * EMB);
    float* ad = agg + (size_t)dst * EMB;

    #pragma unroll
    for (int it = 0; it < 3; it++) {
        int j4 = it * 32 + lane;          // 96 float4 = 384 floats
        float4 v = xs[j4];
        asm volatile(
            "red.global.add.v4.f32 [%0], {%1,%2,%3,%4};"
            :: "l"(ad + j4 * 4),
               "f"(v.x * norm), "f"(v.y * norm), "f"(v.z * norm), "f"(v.w * norm)
            : "memory");
    }
}

// ---------------------------------------------------------------------------
// Final projection to 2 logits from g_bufA: one warp per node.
// ---------------------------------------------------------------------------
__global__ void out_kernel(
    const float* __restrict__ W, const float* __restrict__ b,
    float* __restrict__ out, int N)
{
    int warp = (blockIdx.x * blockDim.x + threadIdx.x) >> 5;
    int lane = threadIdx.x & 31;
    if (warp >= N) return;

    const float* x = g_bufA + (size_t)warp * EMB;
    float s0 = 0.f, s1 = 0.f;
    #pragma unroll
    for (int it = 0; it < EMB / 32; it++) {
        int j = it * 32 + lane;
        float v = x[j];
        s0 += v * W[j * 2 + 0];
        s1 += v * W[j * 2 + 1];
    }
    #pragma unroll
    for (int o = 16; o > 0; o >>= 1) {
        s0 += __shfl_down_sync(0xFFFFFFFFu, s0, o);
        s1 += __shfl_down_sync(0xFFFFFFFFu, s1, o);
    }
    if (lane == 0) {
        out[(size_t)warp * 2 + 0] = s0 + b[0];
        out[(size_t)warp * 2 + 1] = s1 + b[1];
    }
}

// ---------------------------------------------------------------------------
// Launcher — kernel launches only (graph-capturable, allocation-free)
// ---------------------------------------------------------------------------
extern "C" void kernel_launch(void* const* d_in, const int* in_sizes, int n_in,
                              void* d_out, int out_size)
{
    const float* des = (const float*)d_in[0];
    // d_in[1] = tweet — unused by the reference model
    const float* np_ = (const float*)d_in[2];
    const float* cp  = (const float*)d_in[3];
    const int*   ei  = (const int*)d_in[4];
    const float* W_des = (const float*)d_in[5];  const float* b_des = (const float*)d_in[6];
    const float* W_num = (const float*)d_in[7];  const float* b_num = (const float*)d_in[8];
    const float* W_cat = (const float*)d_in[9];  const float* b_cat = (const float*)d_in[10];
    const float* W_in  = (const float*)d_in[11]; const float* b_in  = (const float*)d_in[12];
    const float* W_g1  = (const float*)d_in[13]; const float* b_g1  = (const float*)d_in[14];
    const float* W_g2  = (const float*)d_in[15]; const float* b_g2  = (const float*)d_in[16];
    const float* W_o1  = (const float*)d_in[17]; const float* b_o1  = (const float*)d_in[18];
    const float* W_o2  = (const float*)d_in[19]; const float* b_o2  = (const float*)d_in[20];

    const int N = in_sizes[0] / 768;
    const int E = in_sizes[4] / 2;

    const int mb = (N + 127) / 128;
    const int total = N * EMB;

    // --- degree / dinv ---
    zero_dinv<<<(N + 255) / 256, 256>>>(N);
    count_deg<<<(E + 255) / 256, 256>>>(ei, E);
    finish_dinv<<<(N + 255) / 256, 256>>>(N);

    // --- feature embedding: bufA = concat of 3 leaky-linears ---
    tgemm<-1, 0, 1, 1><<<dim3(2, mb), 256>>>(des, W_des, b_des, N, 768, 128, EMB, 0);
    numcat_kernel<<<(N * 128 + 255) / 256, 256>>>(np_, cp, W_num, b_num, W_cat, b_cat, N);

    // --- input linear: bufB = leaky(bufA @ W_in + b_in) ---
    tgemm<0, 1, 1, 1><<<dim3(6, mb), 256>>>(nullptr, W_in, b_in, N, EMB, EMB, EMB, 0);

    // --- GCN conv 1: bufC = bufB @ W_g1 ; bufA = agg(bufC) + b_g1 ---
    tgemm<1, 2, 0, 0><<<dim3(6, mb), 256>>>(nullptr, W_g1, nullptr, N, EMB, EMB, EMB, 0);
    agg_init<2, 0><<<(total + 255) / 256, 256>>>(b_g1, total);
    edge_scatter<2, 0><<<(int)(((size_t)E * 32 + 255) / 256), 256>>>(ei, E);

    // --- GCN conv 2: bufC = bufA @ W_g2 ; bufB = agg(bufC) + b_g2 ---
    tgemm<0, 2, 0, 0><<<dim3(6, mb), 256>>>(nullptr, W_g2, nullptr, N, EMB, EMB, EMB, 0);
    agg_init<2, 1><<<(total + 255) / 256, 256>>>(b_g2, total);
    edge_scatter<2, 1><<<(int)(((size_t)E * 32 + 255) / 256), 256>>>(ei, E);

    // --- output head: bufA = leaky(bufB @ W_o1 + b_o1); out = bufA @ W_o2 + b_o2 ---
    tgemm<1, 0, 1, 1><<<dim3(6, mb), 256>>>(nullptr, W_o1, b_o1, N, EMB, EMB, EMB, 0);
    out_kernel<<<(int)(((size_t)N * 32 + 255) / 256), 256>>>(W_o2, b_o2, (float*)d_out, N);
}

// round 4
// speedup vs baseline: 3.9208x; 2.0871x over previous
#include <cuda_runtime.h>
#include <cstddef>
#include <cstdint>

#define EMB 384
#define NMAX 50000
#define EMAX 800000

// Scratch (static __device__ arrays; no allocation anywhere)
__device__ float g_bufA[(size_t)NMAX * EMB];
__device__ float g_bufB[(size_t)NMAX * EMB];
__device__ float g_bufC[(size_t)NMAX * EMB];
__device__ float g_dinv[NMAX];
__device__ int   g_deg[NMAX];
__device__ int   g_rowptr[NMAX + 1];
__device__ int   g_cnt[NMAX];
__device__ int   g_csr[EMAX];

template <int SEL>
__device__ __forceinline__ float* BUF() {
    if constexpr (SEL == 0) return g_bufA;
    else if constexpr (SEL == 1) return g_bufB;
    else return g_bufC;
}

__device__ __forceinline__ float leaky01(float x) { return x > 0.f ? x : 0.01f * x; }

__device__ __forceinline__ uint32_t f2tf(float x) {
    uint32_t u;
    asm("cvt.rna.tf32.f32 %0, %1;" : "=r"(u) : "f"(x));
    return u;
}

__device__ __forceinline__ void cp_async16(void* smem_dst, const void* gsrc, int src_bytes) {
    uint32_t saddr = (uint32_t)__cvta_generic_to_shared(smem_dst);
    asm volatile("cp.async.cg.shared.global [%0], [%1], 16, %2;"
                 :: "r"(saddr), "l"(gsrc), "r"(src_bytes) : "memory");
}
#define CP_COMMIT() asm volatile("cp.async.commit_group;" ::: "memory")
#define CP_WAIT1()  asm volatile("cp.async.wait_group 1;" ::: "memory")
#define CP_WAIT0()  asm volatile("cp.async.wait_group 0;" ::: "memory")

__device__ __forceinline__ void mma_tf32(
    float& c0, float& c1, float& c2, float& c3,
    uint32_t a0, uint32_t a1, uint32_t a2, uint32_t a3,
    uint32_t b0, uint32_t b1)
{
    asm volatile(
        "mma.sync.aligned.m16n8k8.row.col.f32.tf32.tf32.f32 "
        "{%0,%1,%2,%3}, {%4,%5,%6,%7}, {%8,%9}, {%0,%1,%2,%3};"
        : "+f"(c0), "+f"(c1), "+f"(c2), "+f"(c3)
        : "r"(a0), "r"(a1), "r"(a2), "r"(a3), "r"(b0), "r"(b1));
}

// ---------------------------------------------------------------------------
// tf32 tensor-core GEMM, cp.async double-buffered.
// C[M,Nc] = act(A[M,K] @ B[K,Nc] + bias). BM=128, BN=64, BK=16, 2 stages.
// 8 warps: 4(m) x 2(n); each warp 32x32 via 2x4 m16n8k8 tiles.
// Requires K%16==0, Nc%64==0, M*K and K*Nc 16B-aligned rows (K,Nc mult of 4).
// ---------------------------------------------------------------------------
template <int SRC, int DST, int HAS_BIAS, int ACT>
__global__ void __launch_bounds__(256) tgemm(
    const float* __restrict__ Ain, const float* __restrict__ B,
    const float* __restrict__ bias,
    int M, int K, int Nc, int ldc, int coff)
{
    const float* __restrict__ A;
    if constexpr (SRC < 0) A = Ain; else A = BUF<SRC>();
    float* __restrict__ C = BUF<DST>();

    __shared__ float As[2][128][20];   // row-major [m][k], stride 20 (conflict-free)
    __shared__ float Bs[2][16][72];    // [k][n], stride 72 (conflict-free)

    const int tid = threadIdx.x;
    const int lane = tid & 31;
    const int warp = tid >> 5;
    const int warp_m = warp & 3;
    const int warp_n = warp >> 2;
    const int gid = lane >> 2;
    const int tig = lane & 3;

    const int row0 = blockIdx.y * 128;
    const int col0 = blockIdx.x * 64;

    float c[2][4][4];
    #pragma unroll
    for (int i = 0; i < 2; i++)
        #pragma unroll
        for (int j = 0; j < 4; j++)
            #pragma unroll
            for (int q = 0; q < 4; q++) c[i][j][q] = 0.f;

    auto load_tile = [&](int kt, int buf) {
        const int k0 = kt * 16;
        // A: 128 rows x 16 floats = 512 x 16B segments, 2 per thread
        #pragma unroll
        for (int i = 0; i < 2; i++) {
            int seg = tid + i * 256;
            int r = seg >> 2;
            int cf = (seg & 3) * 4;
            int gr = row0 + r;
            int grc = gr < M ? gr : (M - 1);
            cp_async16(&As[buf][r][cf],
                       A + (size_t)grc * K + k0 + cf,
                       gr < M ? 16 : 0);
        }
        // B: 16 rows x 64 floats = 256 x 16B segments, 1 per thread
        {
            int r = tid >> 4;
            int cf = (tid & 15) * 4;
            cp_async16(&Bs[buf][r][cf],
                       B + (size_t)(k0 + r) * Nc + col0 + cf, 16);
        }
    };

    auto compute = [&](int buf) {
        #pragma unroll
        for (int ks = 0; ks < 16; ks += 8) {
            uint32_t af[2][4], bf[4][2];
            #pragma unroll
            for (int tm = 0; tm < 2; tm++) {
                int mrow = warp_m * 32 + tm * 16 + gid;
                af[tm][0] = f2tf(As[buf][mrow][ks + tig]);
                af[tm][1] = f2tf(As[buf][mrow + 8][ks + tig]);
                af[tm][2] = f2tf(As[buf][mrow][ks + tig + 4]);
                af[tm][3] = f2tf(As[buf][mrow + 8][ks + tig + 4]);
            }
            #pragma unroll
            for (int tn = 0; tn < 4; tn++) {
                int ncol = warp_n * 32 + tn * 8 + gid;
                bf[tn][0] = f2tf(Bs[buf][ks + tig][ncol]);
                bf[tn][1] = f2tf(Bs[buf][ks + tig + 4][ncol]);
            }
            #pragma unroll
            for (int tm = 0; tm < 2; tm++)
                #pragma unroll
                for (int tn = 0; tn < 4; tn++)
                    mma_tf32(c[tm][tn][0], c[tm][tn][1], c[tm][tn][2], c[tm][tn][3],
                             af[tm][0], af[tm][1], af[tm][2], af[tm][3],
                             bf[tn][0], bf[tn][1]);
        }
    };

    const int KT = K >> 4;
    load_tile(0, 0);
    CP_COMMIT();
    for (int kt = 0; kt < KT; kt++) {
        int buf = kt & 1;
        if (kt + 1 < KT) {
            load_tile(kt + 1, buf ^ 1);
            CP_COMMIT();
            CP_WAIT1();
        } else {
            CP_WAIT0();
        }
        __syncthreads();
        compute(buf);
        __syncthreads();
    }

    // Epilogue
    #pragma unroll
    for (int tm = 0; tm < 2; tm++) {
        int rbase = row0 + warp_m * 32 + tm * 16 + gid;
        #pragma unroll
        for (int tn = 0; tn < 4; tn++) {
            int gc = col0 + warp_n * 32 + tn * 8 + 2 * tig;
            float bx = 0.f, by = 0.f;
            if (HAS_BIAS) { bx = bias[gc]; by = bias[gc + 1]; }
            #pragma unroll
            for (int half = 0; half < 2; half++) {
                int gr = rbase + half * 8;
                if (gr >= M) continue;
                float v0 = c[tm][tn][half * 2 + 0] + bx;
                float v1 = c[tm][tn][half * 2 + 1] + by;
                if (ACT) { v0 = leaky01(v0); v1 = leaky01(v1); }
                *(float2*)(C + (size_t)gr * ldc + coff + gc) = make_float2(v0, v1);
            }
        }
    }
}

// ---------------------------------------------------------------------------
// num/cat feature linears (K=4, K=3) -> concat columns [128:256), [256:384)
// ---------------------------------------------------------------------------
__global__ void numcat_kernel(
    const float* __restrict__ np_, const float* __restrict__ cp,
    const float* __restrict__ Wn, const float* __restrict__ bn,
    const float* __restrict__ Wc, const float* __restrict__ bc, int N)
{
    int i = blockIdx.x * blockDim.x + threadIdx.x;
    int node = i >> 7;
    int col = i & 127;
    if (node >= N) return;

    float s = bn[col];
    #pragma unroll
    for (int k = 0; k < 4; k++) s += np_[node * 4 + k] * Wn[k * 128 + col];
    g_bufA[(size_t)node * EMB + 128 + col] = leaky01(s);

    float t = bc[col];
    #pragma unroll
    for (int k = 0; k < 3; k++) t += cp[node * 3 + k] * Wc[k * 128 + col];
    g_bufA[(size_t)node * EMB + 256 + col] = leaky01(t);
}

// ---------------------------------------------------------------------------
// Degree / dinv / CSR build (edge_index int32; CSR keyed by dst, stores src)
// ---------------------------------------------------------------------------
__global__ void zero_deg(int N)
{
    int i = blockIdx.x * blockDim.x + threadIdx.x;
    if (i < N) g_deg[i] = 0;
}

__global__ void count_deg(const int* __restrict__ ei, int E)
{
    int e = blockIdx.x * blockDim.x + threadIdx.x;
    if (e < E) atomicAdd(&g_deg[ei[E + e]], 1);
}

__global__ void finish_dinv(int N)
{
    int i = blockIdx.x * blockDim.x + threadIdx.x;
    if (i < N) g_dinv[i] = rsqrtf((float)g_deg[i] + 1.0f);
}

// Single-block exclusive scan of g_deg -> g_rowptr; also zeros g_cnt.
__global__ void __launch_bounds__(1024) scan_rowptr(int N)
{
    __shared__ int sums[1024];
    const int t = threadIdx.x;
    const int C = (N + 1023) >> 10;
    const int b = t * C;
    const int e = min(b + C, N);

    int s = 0;
    for (int i = b; i < e; i++) s += g_deg[i];
    sums[t] = s;
    __syncthreads();

    for (int off = 1; off < 1024; off <<= 1) {
        int v = (t >= off) ? sums[t - off] : 0;
        __syncthreads();
        sums[t] += v;
        __syncthreads();
    }

    int run = (t == 0) ? 0 : sums[t - 1];
    for (int i = b; i < e; i++) {
        g_rowptr[i] = run;
        run += g_deg[i];
        g_cnt[i] = 0;
    }
    if (b < N && e == N) g_rowptr[N] = run;
}

__global__ void fill_csr(const int* __restrict__ ei, int E)
{
    int e = blockIdx.x * blockDim.x + threadIdx.x;
    if (e >= E) return;
    int d = ei[E + e];
    int pos = g_rowptr[d] + atomicAdd(&g_cnt[d], 1);
    g_csr[pos] = ei[e];
}

// ---------------------------------------------------------------------------
// GCN gather: one warp per node. agg[n] = sum_{s in in(n)} xw[s]*dinv[s]*dinv[n]
//                                        + xw[n]*dinv[n]^2 + bias
// ---------------------------------------------------------------------------
__device__ __forceinline__ void fma4(float4& a, const float4 v, float n) {
    a.x = fmaf(v.x, n, a.x);
    a.y = fmaf(v.y, n, a.y);
    a.z = fmaf(v.z, n, a.z);
    a.w = fmaf(v.w, n, a.w);
}

template <int SRC, int DST>
__global__ void gcn_gather(const float* __restrict__ bias, int N)
{
    const float* __restrict__ xw = BUF<SRC>();
    float* __restrict__ agg = BUF<DST>();

    int w = (blockIdx.x * blockDim.x + threadIdx.x) >> 5;
    int lane = threadIdx.x & 31;
    if (w >= N) return;

    float din = g_dinv[w];
    float self = din * din;

    const float4* xr = (const float4*)(xw + (size_t)w * EMB);
    const float4* bi = (const float4*)bias;

    float4 a0 = bi[lane], a1 = bi[lane + 32], a2 = bi[lane + 64];
    fma4(a0, xr[lane], self);
    fma4(a1, xr[lane + 32], self);
    fma4(a2, xr[lane + 64], self);

    int p = g_rowptr[w];
    const int pe = g_rowptr[w + 1];

    for (; p + 1 < pe; p += 2) {
        int s0 = g_csr[p], s1 = g_csr[p + 1];
        float n0 = g_dinv[s0] * din;
        float n1 = g_dinv[s1] * din;
        const float4* x0 = (const float4*)(xw + (size_t)s0 * EMB);
        const float4* x1 = (const float4*)(xw + (size_t)s1 * EMB);
        float4 v00 = x0[lane], v01 = x0[lane + 32], v02 = x0[lane + 64];
        float4 v10 = x1[lane], v11 = x1[lane + 32], v12 = x1[lane + 64];
        fma4(a0, v00, n0); fma4(a1, v01, n0); fma4(a2, v02, n0);
        fma4(a0, v10, n1); fma4(a1, v11, n1); fma4(a2, v12, n1);
    }
    if (p < pe) {
        int s0 = g_csr[p];
        float n0 = g_dinv[s0] * din;
        const float4* x0 = (const float4*)(xw + (size_t)s0 * EMB);
        fma4(a0, x0[lane], n0);
        fma4(a1, x0[lane + 32], n0);
        fma4(a2, x0[lane + 64], n0);
    }

    float4* ar = (float4*)(agg + (size_t)w * EMB);
    ar[lane] = a0;
    ar[lane + 32] = a1;
    ar[lane + 64] = a2;
}

// ---------------------------------------------------------------------------
// Final projection to 2 logits from g_bufA: one warp per node.
// ---------------------------------------------------------------------------
__global__ void out_kernel(
    const float* __restrict__ W, const float* __restrict__ b,
    float* __restrict__ out, int N)
{
    int warp = (blockIdx.x * blockDim.x + threadIdx.x) >> 5;
    int lane = threadIdx.x & 31;
    if (warp >= N) return;

    const float* x = g_bufA + (size_t)warp * EMB;
    float s0 = 0.f, s1 = 0.f;
    #pragma unroll
    for (int it = 0; it < EMB / 32; it++) {
        int j = it * 32 + lane;
        float v = x[j];
        s0 += v * W[j * 2 + 0];
        s1 += v * W[j * 2 + 1];
    }
    #pragma unroll
    for (int o = 16; o > 0; o >>= 1) {
        s0 += __shfl_down_sync(0xFFFFFFFFu, s0, o);
        s1 += __shfl_down_sync(0xFFFFFFFFu, s1, o);
    }
    if (lane == 0) {
        out[(size_t)warp * 2 + 0] = s0 + b[0];
        out[(size_t)warp * 2 + 1] = s1 + b[1];
    }
}

// ---------------------------------------------------------------------------
// Launcher — kernel launches only (graph-capturable, allocation-free)
// ---------------------------------------------------------------------------
extern "C" void kernel_launch(void* const* d_in, const int* in_sizes, int n_in,
                              void* d_out, int out_size)
{
    const float* des = (const float*)d_in[0];
    // d_in[1] = tweet — unused by the reference model
    const float* np_ = (const float*)d_in[2];
    const float* cp  = (const float*)d_in[3];
    const int*   ei  = (const int*)d_in[4];
    const float* W_des = (const float*)d_in[5];  const float* b_des = (const float*)d_in[6];
    const float* W_num = (const float*)d_in[7];  const float* b_num = (const float*)d_in[8];
    const float* W_cat = (const float*)d_in[9];  const float* b_cat = (const float*)d_in[10];
    const float* W_in  = (const float*)d_in[11]; const float* b_in  = (const float*)d_in[12];
    const float* W_g1  = (const float*)d_in[13]; const float* b_g1  = (const float*)d_in[14];
    const float* W_g2  = (const float*)d_in[15]; const float* b_g2  = (const float*)d_in[16];
    const float* W_o1  = (const float*)d_in[17]; const float* b_o1  = (const float*)d_in[18];
    const float* W_o2  = (const float*)d_in[19]; const float* b_o2  = (const float*)d_in[20];

    const int N = in_sizes[0] / 768;
    const int E = in_sizes[4] / 2;

    const int mb = (N + 127) / 128;
    const int nwarpgrid = (int)(((size_t)N * 32 + 255) / 256);

    // --- degree / dinv / CSR ---
    zero_deg<<<(N + 255) / 256, 256>>>(N);
    count_deg<<<(E + 255) / 256, 256>>>(ei, E);
    finish_dinv<<<(N + 255) / 256, 256>>>(N);
    scan_rowptr<<<1, 1024>>>(N);
    fill_csr<<<(E + 255) / 256, 256>>>(ei, E);

    // --- feature embedding: bufA = concat of 3 leaky-linears ---
    tgemm<-1, 0, 1, 1><<<dim3(2, mb), 256>>>(des, W_des, b_des, N, 768, 128, EMB, 0);
    numcat_kernel<<<(N * 128 + 255) / 256, 256>>>(np_, cp, W_num, b_num, W_cat, b_cat, N);

    // --- input linear: bufB = leaky(bufA @ W_in + b_in) ---
    tgemm<0, 1, 1, 1><<<dim3(6, mb), 256>>>(nullptr, W_in, b_in, N, EMB, EMB, EMB, 0);

    // --- GCN conv 1: bufC = bufB @ W_g1 ; bufA = gather(bufC) + b_g1 ---
    tgemm<1, 2, 0, 0><<<dim3(6, mb), 256>>>(nullptr, W_g1, nullptr, N, EMB, EMB, EMB, 0);
    gcn_gather<2, 0><<<nwarpgrid, 256>>>(b_g1, N);

    // --- GCN conv 2: bufC = bufA @ W_g2 ; bufB = gather(bufC) + b_g2 ---
    tgemm<0, 2, 0, 0><<<dim3(6, mb), 256>>>(nullptr, W_g2, nullptr, N, EMB, EMB, EMB, 0);
    gcn_gather<2, 1><<<nwarpgrid, 256>>>(b_g2, N);

    // --- output head: bufA = leaky(bufB @ W_o1 + b_o1); out = bufA @ W_o2 + b_o2 ---
    tgemm<1, 0, 1, 1><<<dim3(6, mb), 256>>>(nullptr, W_o1, b_o1, N, EMB, EMB, EMB, 0);
    out_kernel<<<nwarpgrid, 256>>>(W_o2, b_o2, (float*)d_out, N);
}